// round 1
// baseline (speedup 1.0000x reference)
#include <cuda_runtime.h>
#include <cuda_bf16.h>
#include <math.h>

// Shapes (fixed by the problem)
#define NB   4
#define CIN  256
#define HH   64
#define WW   64
#define HW   4096
#define CM   64
#define EOUT 100
#define OUTC 256

// Scratch (device globals; allocation is forbidden)
__device__ float g_t[NB * CM * HW];     // 4 MB   down-conv output
__device__ float g_e[NB * EOUT * HW];   // 6.5 MB encoder logits
__device__ float g_z[NB * OUTC * HW];   // 16 MB  z = W_out @ x (pre-upsample!)

// ---------------------------------------------------------------------------
// Kernel 1/3: 1x1 conv as GEMM.  out[(n*M+m)*HW+pix] = bias[m] + sum_c W[m*C+c]*X[(n*C+c)*HW+pix]
// grid.x = total_pixels/512 (2 pixels per thread), grid.y = M/16, 256 threads.
// ---------------------------------------------------------------------------
__global__ void gemm1x1_kernel(const float* __restrict__ X,
                               const float* __restrict__ Wm,
                               const float* __restrict__ bias,
                               float* __restrict__ out,
                               int C, int M) {
    __shared__ float sW[16 * 256];
    const int m0 = blockIdx.y * 16;
    for (int i = threadIdx.x; i < 16 * C; i += 256)
        sW[i] = Wm[(m0 + i / C) * C + (i % C)];
    __syncthreads();

    const int p0   = blockIdx.x * 512 + threadIdx.x;  // block spans 512 pixels, never crosses image
    const int n    = p0 >> 12;
    const int pix0 = p0 & 4095;
    const int pix1 = pix0 + 256;
    const float* xb = X + (size_t)n * C * HW;

    float a0[16], a1[16];
#pragma unroll
    for (int i = 0; i < 16; i++) {
        float b = bias ? bias[m0 + i] : 0.0f;
        a0[i] = b; a1[i] = b;
    }

    for (int c = 0; c < C; c++) {
        float x0 = xb[c * HW + pix0];
        float x1 = xb[c * HW + pix1];
#pragma unroll
        for (int i = 0; i < 16; i++) {
            float w = sW[i * C + c];
            a0[i] += x0 * w;
            a1[i] += x1 * w;
        }
    }

    float* ob = out + (size_t)n * M * HW;
#pragma unroll
    for (int i = 0; i < 16; i++) {
        ob[(m0 + i) * HW + pix0] = a0[i];
        ob[(m0 + i) * HW + pix1] = a1[i];
    }
}

// ---------------------------------------------------------------------------
// Kernel 2: 3x3 encoder conv  t[4,64,64,64] -> e[4,100,64,64], SAME padding.
// Tile: 8x16 spatial, 20 output channels per block (grid.z = 5 chunks).
// smem: t-tile [64][10][18] (46 KB) + W chunk [20][64][12] padded for float4 (60 KB).
// Inner loop per (m, q): 3x LDS.128 + 9 FFMA.
// ---------------------------------------------------------------------------
#define CONV_CHUNK 20
#define CONV_SMEM  ((64 * 10 * 18 + CONV_CHUNK * 64 * 12) * 4)

__global__ void enc_conv_kernel(const float* __restrict__ T,
                                const float* __restrict__ Wenc,
                                const float* __restrict__ benc,
                                float* __restrict__ E) {
    extern __shared__ float smem[];
    float* sT = smem;                   // [64][10][18]
    float* sW = smem + 64 * 10 * 18;    // [20][64][12]

    const int wtile = blockIdx.x;          // 0..3
    const int n     = blockIdx.y >> 3;     // 0..3
    const int htile = blockIdx.y & 7;      // 0..7
    const int ch0   = blockIdx.z * CONV_CHUNK;
    const int tid   = threadIdx.x;         // 128 threads

    const int h0 = htile * 8 - 1, w0 = wtile * 16 - 1;
    for (int idx = tid; idx < 64 * 10 * 18; idx += 128) {
        int ch = idx / 180, rem = idx % 180;
        int r = rem / 18, col = rem % 18;
        int gr = h0 + r, gc = w0 + col;
        float v = 0.0f;
        if (gr >= 0 && gr < HH && gc >= 0 && gc < WW)
            v = T[((n * CM + ch) * HH + gr) * WW + gc];
        sT[idx] = v;
    }
    for (int idx = tid; idx < CONV_CHUNK * 64 * 12; idx += 128) {
        int q = idx / 768, rem = idx % 768;
        int m = rem / 12, tp = rem % 12;
        sW[idx] = (tp < 9) ? Wenc[((ch0 + q) * CM + m) * 9 + tp] : 0.0f;
    }
    __syncthreads();

    const int ty = tid >> 4, tx = tid & 15;
    float acc[CONV_CHUNK];
#pragma unroll
    for (int q = 0; q < CONV_CHUNK; q++) acc[q] = benc[ch0 + q];

    for (int m = 0; m < 64; m++) {
        const float* tb = sT + m * 180 + ty * 18 + tx;
        float t0 = tb[0],  t1 = tb[1],  t2 = tb[2];
        float t3 = tb[18], t4 = tb[19], t5 = tb[20];
        float t6 = tb[36], t7 = tb[37], t8 = tb[38];
        const float4* wb = (const float4*)(sW + m * 12);
#pragma unroll
        for (int q = 0; q < CONV_CHUNK; q++) {
            float4 w0 = wb[q * 192 + 0];
            float4 w1 = wb[q * 192 + 1];
            float4 w2 = wb[q * 192 + 2];
            acc[q] += t0 * w0.x + t1 * w0.y + t2 * w0.z
                    + t3 * w0.w + t4 * w1.x + t5 * w1.y
                    + t6 * w1.z + t7 * w1.w + t8 * w2.x;
        }
    }

    const int h = htile * 8 + ty, w = wtile * 16 + tx;
#pragma unroll
    for (int q = 0; q < CONV_CHUNK; q++)
        E[((n * EOUT + ch0 + q) * HH + h) * WW + w] = acc[q];
}

// ---------------------------------------------------------------------------
// Kernel 4: fused softmax + reassembly + pixel-shuffle + bias.
// block = (n,h) x chalf; 256 threads = 64 w-positions x 4 parallel channels.
// Softmax over the 25 reassembly weights (per subpixel p) held in 100 registers.
// Per channel: 25 smem reads of z-window + 100 FFMA -> 4 output subpixels.
// ---------------------------------------------------------------------------
__global__ void carafe_kernel(const float* __restrict__ E,
                              const float* __restrict__ Z,
                              const float* __restrict__ bout,
                              float* __restrict__ out) {
    __shared__ float sZ[4 * 5 * 68];   // 4 channels x 5 rows x 68 padded cols

    const int nh = blockIdx.x;
    const int n  = nh >> 6;
    const int h  = nh & 63;
    const int chalf = blockIdx.y;      // 0..1
    const int tid = threadIdx.x;
    const int w  = tid & 63;
    const int cq = tid >> 6;           // 0..3

    // ---- load 100 logits for this (n,h,w), softmax over k for each p ----
    float kr[100];
    const float* eb = E + ((size_t)n * EOUT * HW) + h * WW + w;
#pragma unroll
    for (int ch = 0; ch < 100; ch++) kr[ch] = eb[ch * HW];

#pragma unroll
    for (int p = 0; p < 4; p++) {
        float mx = kr[p];
#pragma unroll
        for (int k = 1; k < 25; k++) mx = fmaxf(mx, kr[k * 4 + p]);
        float s = 0.0f;
#pragma unroll
        for (int k = 0; k < 25; k++) {
            float ex = __expf(kr[k * 4 + p] - mx);
            kr[k * 4 + p] = ex;
            s += ex;
        }
        float inv = 1.0f / s;
#pragma unroll
        for (int k = 0; k < 25; k++) kr[k * 4 + p] *= inv;
    }

    float2* op = (float2*)out;

    for (int it = 0; it < 32; it++) {
        const int cbase = chalf * 128 + it * 4;
        __syncthreads();
        // stage 4 channels x 5 rows (h-2..h+2) x 68 cols (w: -2..65), zero-padded
        for (int idx = tid; idx < 4 * 5 * 68; idx += 256) {
            int cc = idx / 340, rem = idx % 340;
            int r = rem / 68, col = rem % 68;
            int row = h - 2 + r, wc = col - 2;
            float v = 0.0f;
            if (row >= 0 && row < HH && wc >= 0 && wc < WW)
                v = Z[((n * OUTC + cbase + cc) * HH + row) * WW + wc];
            sZ[idx] = v;
        }
        __syncthreads();

        const int c = cbase + cq;
        float a0 = 0.f, a1 = 0.f, a2 = 0.f, a3 = 0.f;
        const float* zb = sZ + cq * 340 + w;
#pragma unroll
        for (int ki = 0; ki < 5; ki++) {
#pragma unroll
            for (int kj = 0; kj < 5; kj++) {
                float zv = zb[ki * 68 + kj];
                int k4 = (ki * 5 + kj) * 4;
                a0 += zv * kr[k4 + 0];
                a1 += zv * kr[k4 + 1];
                a2 += zv * kr[k4 + 2];
                a3 += zv * kr[k4 + 3];
            }
        }
        float bo = bout[c];
        // out[n, c, 2h+i, 2w+j]; row-pairs as float2
        int base = ((n * OUTC + c) * 128 + 2 * h) * 64 + w;
        op[base]      = make_float2(a0 + bo, a1 + bo);
        op[base + 64] = make_float2(a2 + bo, a3 + bo);
    }
}

// ---------------------------------------------------------------------------
extern "C" void kernel_launch(void* const* d_in, const int* in_sizes, int n_in,
                              void* d_out, int out_size) {
    const float* x  = (const float*)d_in[0];
    const float* Wd = (const float*)d_in[1];
    const float* bd = (const float*)d_in[2];
    const float* We = (const float*)d_in[3];
    const float* be = (const float*)d_in[4];
    const float* Wo = (const float*)d_in[5];
    const float* bo = (const float*)d_in[6];
    float* out = (float*)d_out;

    static float* gt = nullptr;
    static float* ge = nullptr;
    static float* gz = nullptr;
    if (!gt) {
        cudaGetSymbolAddress((void**)&gt, g_t);
        cudaGetSymbolAddress((void**)&ge, g_e);
        cudaGetSymbolAddress((void**)&gz, g_z);
        cudaFuncSetAttribute(enc_conv_kernel,
                             cudaFuncAttributeMaxDynamicSharedMemorySize, CONV_SMEM);
    }

    // 1) t = W_down @ x + b_down            [4,64,64,64]
    gemm1x1_kernel<<<dim3(32, 4), 256>>>(x, Wd, bd, gt, CIN, CM);
    // 2) e = conv3x3(t, W_enc) + b_enc      [4,100,64,64]
    enc_conv_kernel<<<dim3(4, 32, 5), 128, CONV_SMEM>>>(gt, We, be, ge);
    // 3) z = W_out @ x  (1x1 conv BEFORE upsampling -- 4x less work)
    gemm1x1_kernel<<<dim3(32, 16), 256>>>(x, Wo, nullptr, gz, CIN, OUTC);
    // 4) out = reassemble(z, softmax(e)) + b_out   [4,256,128,128]
    carafe_kernel<<<dim3(256, 2), 256>>>(ge, gz, bo, out);
}

// round 3
// speedup vs baseline: 1.5601x; 1.5601x over previous
#include <cuda_runtime.h>
#include <cuda_bf16.h>
#include <math.h>

// Shapes (fixed by the problem)
#define NB   4
#define CIN  256
#define HH   64
#define WW   64
#define HW   4096
#define CM   64
#define EOUT 100
#define OUTC 256

// Scratch (device globals; allocation is forbidden)
__device__ float g_t[NB * CM * HW];     // 4 MB   down-conv output
__device__ float g_e[NB * EOUT * HW];   // 6.5 MB encoder logits
__device__ float g_z[NB * OUTC * HW];   // 16 MB  z = W_out @ x (pre-upsample!)

// ---------------------------------------------------------------------------
// 1x1 conv as GEMM, 4 contiguous pixels per thread (float4), MTILE output
// channels per block.  Weights staged TRANSPOSED in smem ([C][MTILE]) so the
// inner loop is 1 LDG.128 + MTILE/4 LDS.128 broadcasts + 4*MTILE FFMA.
// ---------------------------------------------------------------------------
template<int MTILE>
__global__ void __launch_bounds__(256) gemm1x1_v(
        const float* __restrict__ X, const float* __restrict__ Wm,
        const float* __restrict__ bias, float* __restrict__ out,
        int C, int M) {
    __shared__ float sWt[256 * MTILE];   // [C][MTILE]
    const int m0 = blockIdx.y * MTILE;
    for (int idx = threadIdx.x; idx < C * MTILE; idx += 256)
        sWt[idx] = Wm[(m0 + (idx % MTILE)) * C + (idx / MTILE)];
    __syncthreads();

    const int p0  = (blockIdx.x * 256 + threadIdx.x) * 4;  // 4 contiguous pixels
    const int n   = p0 >> 12;
    const int pix = p0 & 4095;
    const float4* xb = (const float4*)(X + (size_t)n * C * HW) + (pix >> 2);

    float4 acc[MTILE];
#pragma unroll
    for (int i = 0; i < MTILE; i++) {
        float b = bias ? bias[m0 + i] : 0.0f;
        acc[i] = make_float4(b, b, b, b);
    }

    const float4* sW4 = (const float4*)sWt;
#pragma unroll 2
    for (int c = 0; c < C; c++) {
        float4 xv = xb[c * (HW / 4)];
#pragma unroll
        for (int j = 0; j < MTILE / 4; j++) {
            float4 wv = sW4[c * (MTILE / 4) + j];
            acc[j*4+0].x += xv.x * wv.x; acc[j*4+0].y += xv.y * wv.x;
            acc[j*4+0].z += xv.z * wv.x; acc[j*4+0].w += xv.w * wv.x;
            acc[j*4+1].x += xv.x * wv.y; acc[j*4+1].y += xv.y * wv.y;
            acc[j*4+1].z += xv.z * wv.y; acc[j*4+1].w += xv.w * wv.y;
            acc[j*4+2].x += xv.x * wv.z; acc[j*4+2].y += xv.y * wv.z;
            acc[j*4+2].z += xv.z * wv.z; acc[j*4+2].w += xv.w * wv.z;
            acc[j*4+3].x += xv.x * wv.w; acc[j*4+3].y += xv.y * wv.w;
            acc[j*4+3].z += xv.z * wv.w; acc[j*4+3].w += xv.w * wv.w;
        }
    }

    float4* ob = (float4*)(out + (size_t)n * M * HW) + (pix >> 2);
#pragma unroll
    for (int i = 0; i < MTILE; i++)
        ob[(m0 + i) * (HW / 4)] = acc[i];
}

// ---------------------------------------------------------------------------
// 3x3 encoder conv  t[4,64,64,64] -> e[4,100,64,64], SAME padding.
// 8x32 spatial tile, 20 out-channels, input channels chunked by 16 so smem is
// 37 KB (4+ blocks/SM instead of the old 1).  256 threads.
// ---------------------------------------------------------------------------
#define QC  20
#define ICC 16

__global__ void __launch_bounds__(256) enc_conv_kernel(
        const float* __restrict__ T, const float* __restrict__ Wenc,
        const float* __restrict__ benc, float* __restrict__ E) {
    __shared__ float sT[ICC * 10 * 34];   // 5440 floats
    __shared__ float sW[QC * ICC * 12];   // 3840 floats (9 taps padded to 12)

    const int wtile = blockIdx.x;          // 0..1  (32-wide tiles)
    const int n     = blockIdx.y >> 3;     // 0..3
    const int htile = blockIdx.y & 7;      // 0..7  (8-high tiles)
    const int ch0   = blockIdx.z * QC;
    const int tid   = threadIdx.x;
    const int ty    = tid >> 5, tx = tid & 31;
    const int h0 = htile * 8 - 1, w0 = wtile * 32 - 1;

    float acc[QC];
#pragma unroll
    for (int q = 0; q < QC; q++) acc[q] = benc[ch0 + q];

    for (int icc = 0; icc < CM / ICC; icc++) {
        const int ic0 = icc * ICC;
        __syncthreads();
        for (int idx = tid; idx < ICC * 10 * 34; idx += 256) {
            int ch = idx / 340, rem = idx % 340;
            int r = rem / 34, col = rem % 34;
            int gr = h0 + r, gc = w0 + col;
            float v = 0.0f;
            if ((unsigned)gr < HH && (unsigned)gc < WW)
                v = T[((n * CM + ic0 + ch) * HH + gr) * WW + gc];
            sT[idx] = v;
        }
        for (int idx = tid; idx < QC * ICC * 12; idx += 256) {
            int q = idx / 192, rem = idx % 192;
            int m = rem / 12, tp = rem % 12;
            sW[idx] = (tp < 9) ? Wenc[((ch0 + q) * CM + ic0 + m) * 9 + tp] : 0.0f;
        }
        __syncthreads();

        for (int m = 0; m < ICC; m++) {
            const float* tb = sT + m * 340 + ty * 34 + tx;
            float t0 = tb[0],  t1 = tb[1],  t2 = tb[2];
            float t3 = tb[34], t4 = tb[35], t5 = tb[36];
            float t6 = tb[68], t7 = tb[69], t8 = tb[70];
            const float4* wb = (const float4*)sW + m * 3;
#pragma unroll
            for (int q = 0; q < QC; q++) {
                float4 w0 = wb[q * 48 + 0];
                float4 w1 = wb[q * 48 + 1];
                float4 w2 = wb[q * 48 + 2];
                acc[q] += t0 * w0.x + t1 * w0.y + t2 * w0.z
                        + t3 * w0.w + t4 * w1.x + t5 * w1.y
                        + t6 * w1.z + t7 * w1.w + t8 * w2.x;
            }
        }
    }

    const int h = htile * 8 + ty, w = wtile * 32 + tx;
#pragma unroll
    for (int q = 0; q < QC; q++)
        E[((n * EOUT + ch0 + q) * HH + h) * WW + w] = acc[q];
}

// ---------------------------------------------------------------------------
// Fused softmax + reassembly + pixel-shuffle + bias.
// 256 threads = 64 w  x  2 subpixel-rows (psel)  x  2 channel-slots (cslot).
// Each thread keeps 50 softmax weights in registers (2 subpixels x 25 taps)
// and processes 2 channels per stage -> regs ~80, double the old occupancy.
// Staging is shift-only addressing: float4 interior + scalar halo.
// ---------------------------------------------------------------------------
__global__ void __launch_bounds__(256) carafe_kernel(
        const float* __restrict__ E, const float* __restrict__ Z,
        const float* __restrict__ bout, float* __restrict__ out) {
    __shared__ float sZ[4 * 5 * 72];   // 4 ch x 5 rows x 72 cols (interior at 4..67)

    const int nh = blockIdx.x;
    const int n  = nh >> 6;
    const int h  = nh & 63;
    const int chalf = blockIdx.y;       // 0..1
    const int tid   = threadIdx.x;
    const int w     = tid & 63;
    const int psel  = (tid >> 6) & 1;   // subpixel row i
    const int cslot = tid >> 7;         // 0..1

    // ---- softmax weights for subpixels p0=2*psel, p0+1 (50 registers) ----
    const int p0 = 2 * psel;
    float kr[50];
    const float* eb = E + (size_t)n * EOUT * HW + h * WW + w;
#pragma unroll
    for (int k = 0; k < 25; k++) {
        kr[k * 2 + 0] = eb[(k * 4 + p0 + 0) * HW];
        kr[k * 2 + 1] = eb[(k * 4 + p0 + 1) * HW];
    }
#pragma unroll
    for (int pp = 0; pp < 2; pp++) {
        float mx = kr[pp];
#pragma unroll
        for (int k = 1; k < 25; k++) mx = fmaxf(mx, kr[k * 2 + pp]);
        float s = 0.0f;
#pragma unroll
        for (int k = 0; k < 25; k++) {
            float ex = __expf(kr[k * 2 + pp] - mx);
            kr[k * 2 + pp] = ex;
            s += ex;
        }
        float inv = 1.0f / s;
#pragma unroll
        for (int k = 0; k < 25; k++) kr[k * 2 + pp] *= inv;
    }

    // staging role constants (shift-only)
    const int lane64 = tid & 63;
    const int sch    = tid >> 6;            // channel slot for interior f4 staging
    const int hch    = tid >> 5;            // channel for halo (tid<128)
    const int t2     = tid & 31;
    float2* op = (float2*)out;
    float4* sZ4 = (float4*)sZ;

    for (int it = 0; it < 32; it++) {
        const int cbase = chalf * 128 + it * 4;
        __syncthreads();

        // ---- interior: 4ch x 5r x 16 float4 (320 f4, shift-only indexing) ----
        {
            const float4* zc = (const float4*)(Z +
                ((size_t)(n * OUTC + cbase + sch) * HH) * WW);
            int r = lane64 >> 4, g = lane64 & 15;
            int row = h - 2 + r;
            float4 v = make_float4(0.f, 0.f, 0.f, 0.f);
            if ((unsigned)row < HH) v = zc[row * 16 + g];
            sZ4[sch * 90 + r * 18 + 1 + g] = v;
            if (lane64 < 16) {                 // r = 4 remainder
                int row2 = h + 2;
                float4 v2 = make_float4(0.f, 0.f, 0.f, 0.f);
                if ((unsigned)row2 < HH) v2 = zc[row2 * 16 + lane64];
                sZ4[sch * 90 + 4 * 18 + 1 + lane64] = v2;
            }
        }
        // ---- halo: 4ch x 5r x {-2,-1,64,65} (80 scalars) ----
        if (tid < 128 && t2 < 20) {
            int r = t2 >> 2, cc = t2 & 3;
            int row = h - 2 + r;
            int wc = (cc < 2) ? cc - 2 : 62 + cc;
            float v = 0.0f;
            if ((unsigned)row < HH && (unsigned)wc < WW)
                v = Z[((size_t)(n * OUTC + cbase + hch) * HH + row) * WW + wc];
            sZ[hch * 360 + r * 72 + ((cc < 2) ? cc + 2 : 66 + cc)] = v;
        }
        __syncthreads();

        const int c0 = cbase + 2 * cslot;
        const float* zb = sZ + (2 * cslot) * 360 + (w + 2);
        float a00 = 0.f, a01 = 0.f, a10 = 0.f, a11 = 0.f;
#pragma unroll
        for (int ki = 0; ki < 5; ki++) {
#pragma unroll
            for (int kj = 0; kj < 5; kj++) {
                int kk = ki * 5 + kj;
                float z0 = zb[ki * 72 + kj];
                float z1 = zb[360 + ki * 72 + kj];
                a00 += z0 * kr[kk * 2 + 0];
                a01 += z0 * kr[kk * 2 + 1];
                a10 += z1 * kr[kk * 2 + 0];
                a11 += z1 * kr[kk * 2 + 1];
            }
        }
        float b0 = __ldg(bout + c0), b1 = __ldg(bout + c0 + 1);
        int row = 2 * h + psel;
        op[((n * OUTC + c0    ) * 128 + row) * 64 + w] = make_float2(a00 + b0, a01 + b0);
        op[((n * OUTC + c0 + 1) * 128 + row) * 64 + w] = make_float2(a10 + b1, a11 + b1);
    }
}

// ---------------------------------------------------------------------------
extern "C" void kernel_launch(void* const* d_in, const int* in_sizes, int n_in,
                              void* d_out, int out_size) {
    const float* x  = (const float*)d_in[0];
    const float* Wd = (const float*)d_in[1];
    const float* bd = (const float*)d_in[2];
    const float* We = (const float*)d_in[3];
    const float* be = (const float*)d_in[4];
    const float* Wo = (const float*)d_in[5];
    const float* bo = (const float*)d_in[6];
    float* out = (float*)d_out;

    static float* gt = nullptr;
    static float* ge = nullptr;
    static float* gz = nullptr;
    if (!gt) {
        cudaGetSymbolAddress((void**)&gt, g_t);
        cudaGetSymbolAddress((void**)&ge, g_e);
        cudaGetSymbolAddress((void**)&gz, g_z);
    }

    // 1) t = W_down @ x + b_down            [4,64,64,64]
    gemm1x1_v<8><<<dim3(16, 8), 256>>>(x, Wd, bd, gt, CIN, CM);
    // 2) e = conv3x3(t, W_enc) + b_enc      [4,100,64,64]
    enc_conv_kernel<<<dim3(2, 32, 5), 256>>>(gt, We, be, ge);
    // 3) z = W_out @ x  (1x1 conv BEFORE upsampling -- 4x less work)
    gemm1x1_v<16><<<dim3(16, 16), 256>>>(x, Wo, nullptr, gz, CIN, OUTC);
    // 4) out = reassemble(z, softmax(e)) + b_out   [4,256,128,128]
    carafe_kernel<<<dim3(256, 2), 256>>>(ge, gz, bo, out);
}

// round 4
// speedup vs baseline: 1.6737x; 1.0728x over previous
#include <cuda_runtime.h>
#include <cuda_bf16.h>
#include <math.h>

// Shapes (fixed by the problem)
#define NB   4
#define CIN  256
#define HH   64
#define WW   64
#define HW   4096
#define CM   64
#define EOUT 100
#define OUTC 256

// Scratch (device globals; allocation is forbidden)
__device__ float g_t[NB * CM * HW];     // 4 MB   down-conv output
__device__ float g_e[NB * EOUT * HW];   // 6.5 MB encoder logits
__device__ float g_z[NB * OUTC * HW];   // 16 MB  z = W_out @ x (pre-upsample!)

// ---------------------------------------------------------------------------
// 1x1 conv as GEMM, 4 contiguous pixels per thread (float4), MTILE output
// channels per block.  Weights staged TRANSPOSED in smem ([C][MTILE]).
// ---------------------------------------------------------------------------
template<int MTILE>
__global__ void __launch_bounds__(256) gemm1x1_v(
        const float* __restrict__ X, const float* __restrict__ Wm,
        const float* __restrict__ bias, float* __restrict__ out,
        int C, int M) {
    __shared__ float sWt[256 * MTILE];   // [C][MTILE]
    const int m0 = blockIdx.y * MTILE;
    for (int idx = threadIdx.x; idx < C * MTILE; idx += 256)
        sWt[idx] = Wm[(m0 + (idx % MTILE)) * C + (idx / MTILE)];
    __syncthreads();

    const int p0  = (blockIdx.x * 256 + threadIdx.x) * 4;  // 4 contiguous pixels
    const int n   = p0 >> 12;
    const int pix = p0 & 4095;
    const float4* xb = (const float4*)(X + (size_t)n * C * HW) + (pix >> 2);

    float4 acc[MTILE];
#pragma unroll
    for (int i = 0; i < MTILE; i++) {
        float b = bias ? bias[m0 + i] : 0.0f;
        acc[i] = make_float4(b, b, b, b);
    }

    const float4* sW4 = (const float4*)sWt;
#pragma unroll 2
    for (int c = 0; c < C; c++) {
        float4 xv = xb[c * (HW / 4)];
#pragma unroll
        for (int j = 0; j < MTILE / 4; j++) {
            float4 wv = sW4[c * (MTILE / 4) + j];
            acc[j*4+0].x += xv.x * wv.x; acc[j*4+0].y += xv.y * wv.x;
            acc[j*4+0].z += xv.z * wv.x; acc[j*4+0].w += xv.w * wv.x;
            acc[j*4+1].x += xv.x * wv.y; acc[j*4+1].y += xv.y * wv.y;
            acc[j*4+1].z += xv.z * wv.y; acc[j*4+1].w += xv.w * wv.y;
            acc[j*4+2].x += xv.x * wv.z; acc[j*4+2].y += xv.y * wv.z;
            acc[j*4+2].z += xv.z * wv.z; acc[j*4+2].w += xv.w * wv.z;
            acc[j*4+3].x += xv.x * wv.w; acc[j*4+3].y += xv.y * wv.w;
            acc[j*4+3].z += xv.z * wv.w; acc[j*4+3].w += xv.w * wv.w;
        }
    }

    float4* ob = (float4*)(out + (size_t)n * M * HW) + (pix >> 2);
#pragma unroll
    for (int i = 0; i < MTILE; i++)
        ob[(m0 + i) * (HW / 4)] = acc[i];
}

// ---------------------------------------------------------------------------
// 3x3 encoder conv  t[4,64,64,64] -> e[4,100,64,64], SAME padding.
// 16x32 spatial tile, 2 output rows per thread (rows ty, ty+8): weight LDS
// amortized over 2x FFMA.  Input channels chunked by 8 -> 27 KB static smem.
// ---------------------------------------------------------------------------
#define QC  20
#define ICC 8

__global__ void __launch_bounds__(256) enc_conv_kernel(
        const float* __restrict__ T, const float* __restrict__ Wenc,
        const float* __restrict__ benc, float* __restrict__ E) {
    __shared__ float sT[ICC * 18 * 34];   // 4896 floats
    __shared__ float sW[QC * ICC * 12];   // 1920 floats (9 taps padded to 12)

    const int wtile = blockIdx.x;          // 0..1  (32-wide tiles)
    const int n     = blockIdx.y >> 2;     // 0..3
    const int htile = blockIdx.y & 3;      // 0..3  (16-high tiles)
    const int ch0   = blockIdx.z * QC;
    const int tid   = threadIdx.x;
    const int ty    = tid >> 5, tx = tid & 31;
    const int h0 = htile * 16 - 1, w0 = wtile * 32 - 1;

    float acc[2 * QC];
#pragma unroll
    for (int q = 0; q < QC; q++) {
        float b = benc[ch0 + q];
        acc[q] = b; acc[QC + q] = b;
    }

    for (int icc = 0; icc < CM / ICC; icc++) {
        const int ic0 = icc * ICC;
        __syncthreads();
        for (int idx = tid; idx < ICC * 18 * 34; idx += 256) {
            int ch = idx / 612, rem = idx % 612;
            int r = rem / 34, col = rem % 34;
            int gr = h0 + r, gc = w0 + col;
            float v = 0.0f;
            if ((unsigned)gr < HH && (unsigned)gc < WW)
                v = T[((n * CM + ic0 + ch) * HH + gr) * WW + gc];
            sT[idx] = v;
        }
        for (int idx = tid; idx < QC * ICC * 12; idx += 256) {
            int q = idx / (ICC * 12), rem = idx % (ICC * 12);
            int m = rem / 12, tp = rem % 12;
            sW[idx] = (tp < 9) ? Wenc[((ch0 + q) * CM + ic0 + m) * 9 + tp] : 0.0f;
        }
        __syncthreads();

#pragma unroll
        for (int m = 0; m < ICC; m++) {
            const float* tb = sT + m * 612 + ty * 34 + tx;
            float t0 = tb[0],  t1 = tb[1],  t2 = tb[2];
            float t3 = tb[34], t4 = tb[35], t5 = tb[36];
            float t6 = tb[68], t7 = tb[69], t8 = tb[70];
            const float* ub = tb + 8 * 34;
            float u0 = ub[0],  u1 = ub[1],  u2 = ub[2];
            float u3 = ub[34], u4 = ub[35], u5 = ub[36];
            float u6 = ub[68], u7 = ub[69], u8 = ub[70];
            const float4* wb = (const float4*)sW + m * 3;
#pragma unroll
            for (int q = 0; q < QC; q++) {
                float4 w0 = wb[q * (ICC * 3) + 0];
                float4 w1 = wb[q * (ICC * 3) + 1];
                float4 w2 = wb[q * (ICC * 3) + 2];
                acc[q] += t0 * w0.x + t1 * w0.y + t2 * w0.z
                        + t3 * w0.w + t4 * w1.x + t5 * w1.y
                        + t6 * w1.z + t7 * w1.w + t8 * w2.x;
                acc[QC + q] += u0 * w0.x + u1 * w0.y + u2 * w0.z
                             + u3 * w0.w + u4 * w1.x + u5 * w1.y
                             + u6 * w1.z + u7 * w1.w + u8 * w2.x;
            }
        }
    }

    const int h = htile * 16 + ty, w = wtile * 32 + tx;
#pragma unroll
    for (int q = 0; q < QC; q++) {
        E[((n * EOUT + ch0 + q) * HH + h    ) * WW + w] = acc[q];
        E[((n * EOUT + ch0 + q) * HH + h + 8) * WW + w] = acc[QC + q];
    }
}

// ---------------------------------------------------------------------------
// Fused softmax + reassembly + pixel-shuffle + bias, double-buffered staging.
// 256 threads = 64 w  x  2 subpixel-rows (psel)  x  2 channel-slots (cslot).
// One __syncthreads per channel-group; next group's LDGs overlap compute.
// ---------------------------------------------------------------------------
__global__ void __launch_bounds__(256) carafe_kernel(
        const float* __restrict__ E, const float* __restrict__ Z,
        const float* __restrict__ bout, float* __restrict__ out) {
    __shared__ float sZ[2][4 * 5 * 72];   // 2 buffers x 4 ch x 5 rows x 72 cols

    const int nh = blockIdx.x;
    const int n  = nh >> 6;
    const int h  = nh & 63;
    const int chalf = blockIdx.y;       // 0..1
    const int tid   = threadIdx.x;
    const int w     = tid & 63;
    const int psel  = (tid >> 6) & 1;   // subpixel row i
    const int cslot = tid >> 7;         // 0..1

    // ---- softmax weights for subpixels p0=2*psel, p0+1 (50 registers) ----
    const int p0 = 2 * psel;
    float kr[50];
    const float* eb = E + (size_t)n * EOUT * HW + h * WW + w;
#pragma unroll
    for (int k = 0; k < 25; k++) {
        kr[k * 2 + 0] = eb[(k * 4 + p0 + 0) * HW];
        kr[k * 2 + 1] = eb[(k * 4 + p0 + 1) * HW];
    }
#pragma unroll
    for (int pp = 0; pp < 2; pp++) {
        float mx = kr[pp];
#pragma unroll
        for (int k = 1; k < 25; k++) mx = fmaxf(mx, kr[k * 2 + pp]);
        float s = 0.0f;
#pragma unroll
        for (int k = 0; k < 25; k++) {
            float ex = __expf(kr[k * 2 + pp] - mx);
            kr[k * 2 + pp] = ex;
            s += ex;
        }
        float inv = 1.0f / s;
#pragma unroll
        for (int k = 0; k < 25; k++) kr[k * 2 + pp] *= inv;
    }

    // staging role constants (shift-only)
    const int lane64 = tid & 63;
    const int sch    = tid >> 6;            // channel slot for interior f4 staging
    const int hch    = tid >> 5;            // channel for halo (tid<128)
    const int t2     = tid & 31;
    float2* op = (float2*)out;

    auto stage = [&](int it, int buf) {
        const int cbase = chalf * 128 + it * 4;
        float4* sZ4 = (float4*)sZ[buf];
        // interior: 4ch x 5r x 16 float4
        const float4* zc = (const float4*)(Z +
            ((size_t)(n * OUTC + cbase + sch) * HH) * WW);
        int r = lane64 >> 4, g = lane64 & 15;
        int row = h - 2 + r;
        float4 v = make_float4(0.f, 0.f, 0.f, 0.f);
        if ((unsigned)row < HH) v = zc[row * 16 + g];
        sZ4[sch * 90 + r * 18 + 1 + g] = v;
        if (lane64 < 16) {                 // r = 4 remainder
            int row2 = h + 2;
            float4 v2 = make_float4(0.f, 0.f, 0.f, 0.f);
            if ((unsigned)row2 < HH) v2 = zc[row2 * 16 + lane64];
            sZ4[sch * 90 + 4 * 18 + 1 + lane64] = v2;
        }
        // halo: 4ch x 5r x {-2,-1,64,65}
        if (tid < 128 && t2 < 20) {
            int rr = t2 >> 2, cc = t2 & 3;
            int hrow = h - 2 + rr;
            int wc = (cc < 2) ? cc - 2 : 62 + cc;
            float hv = 0.0f;
            if ((unsigned)hrow < HH && (unsigned)wc < WW)
                hv = Z[((size_t)(n * OUTC + cbase + hch) * HH + hrow) * WW + wc];
            sZ[buf][hch * 360 + rr * 72 + ((cc < 2) ? cc + 2 : 66 + cc)] = hv;
        }
    };

    stage(0, 0);
    __syncthreads();

    for (int it = 0; it < 32; it++) {
        if (it < 31) stage(it + 1, (it + 1) & 1);

        const int cbase = chalf * 128 + it * 4;
        const int c0 = cbase + 2 * cslot;
        const float* zb = sZ[it & 1] + (2 * cslot) * 360 + (w + 2);
        float a00 = 0.f, a01 = 0.f, a10 = 0.f, a11 = 0.f;
#pragma unroll
        for (int ki = 0; ki < 5; ki++) {
#pragma unroll
            for (int kj = 0; kj < 5; kj++) {
                int kk = ki * 5 + kj;
                float z0 = zb[ki * 72 + kj];
                float z1 = zb[360 + ki * 72 + kj];
                a00 += z0 * kr[kk * 2 + 0];
                a01 += z0 * kr[kk * 2 + 1];
                a10 += z1 * kr[kk * 2 + 0];
                a11 += z1 * kr[kk * 2 + 1];
            }
        }
        float b0 = __ldg(bout + c0), b1 = __ldg(bout + c0 + 1);
        int row = 2 * h + psel;
        op[((n * OUTC + c0    ) * 128 + row) * 64 + w] = make_float2(a00 + b0, a01 + b0);
        op[((n * OUTC + c0 + 1) * 128 + row) * 64 + w] = make_float2(a10 + b1, a11 + b1);
        __syncthreads();
    }
}

// ---------------------------------------------------------------------------
extern "C" void kernel_launch(void* const* d_in, const int* in_sizes, int n_in,
                              void* d_out, int out_size) {
    const float* x  = (const float*)d_in[0];
    const float* Wd = (const float*)d_in[1];
    const float* bd = (const float*)d_in[2];
    const float* We = (const float*)d_in[3];
    const float* be = (const float*)d_in[4];
    const float* Wo = (const float*)d_in[5];
    const float* bo = (const float*)d_in[6];
    float* out = (float*)d_out;

    static float* gt = nullptr;
    static float* ge = nullptr;
    static float* gz = nullptr;
    static cudaStream_t s2;
    static cudaEvent_t ev_fork, ev_join;
    if (!gt) {
        cudaGetSymbolAddress((void**)&gt, g_t);
        cudaGetSymbolAddress((void**)&ge, g_e);
        cudaGetSymbolAddress((void**)&gz, g_z);
        cudaStreamCreateWithFlags(&s2, cudaStreamNonBlocking);
        cudaEventCreateWithFlags(&ev_fork, cudaEventDisableTiming);
        cudaEventCreateWithFlags(&ev_join, cudaEventDisableTiming);
    }

    // Fork: z = W_out @ x is independent of the t/e path -> run concurrently.
    cudaEventRecord(ev_fork, 0);
    cudaStreamWaitEvent(s2, ev_fork, 0);
    gemm1x1_v<16><<<dim3(16, 16), 256, 0, s2>>>(x, Wo, nullptr, gz, CIN, OUTC);
    cudaEventRecord(ev_join, s2);

    // Main path: t = W_down @ x + b ; e = conv3x3(t) + b
    gemm1x1_v<8><<<dim3(16, 8), 256>>>(x, Wd, bd, gt, CIN, CM);
    enc_conv_kernel<<<dim3(2, 16, 5), 256>>>(gt, We, be, ge);

    // Join, then fused reassembly.
    cudaStreamWaitEvent(0, ev_join, 0);
    carafe_kernel<<<dim3(256, 2), 256>>>(ge, gz, bo, out);
}

// round 5
// speedup vs baseline: 1.9530x; 1.1669x over previous
#include <cuda_runtime.h>
#include <cuda_bf16.h>
#include <math.h>

// Shapes (fixed by the problem)
#define NB   4
#define CIN  256
#define HH   64
#define WW   64
#define HW   4096
#define CM   64
#define EOUT 100
#define OUTC 256

typedef unsigned long long u64;

// ---- packed fp32x2 helpers (Blackwell FFMA2 via PTX) ----------------------
__device__ __forceinline__ u64 pack2(float lo, float hi) {
    u64 d; asm("mov.b64 %0,{%1,%2};" : "=l"(d) : "f"(lo), "f"(hi)); return d;
}
__device__ __forceinline__ u64 splat2(float v) {
    u64 d; asm("mov.b64 %0,{%1,%1};" : "=l"(d) : "f"(v)); return d;
}
__device__ __forceinline__ void fma2(u64& acc, u64 a, u64 b) {
    asm("fma.rn.f32x2 %0,%1,%2,%0;" : "+l"(acc) : "l"(a), "l"(b));
}
__device__ __forceinline__ float2 unpack2(u64 d) {
    float2 r; asm("mov.b64 {%0,%1},%2;" : "=f"(r.x), "=f"(r.y) : "l"(d)); return r;
}

// Scratch (device globals; allocation is forbidden)
__device__ float g_t[NB * CM * HW];     // 4 MB   down-conv output
__device__ float g_e[NB * EOUT * HW];   // 6.5 MB encoder logits
__device__ float g_z[NB * OUTC * HW];   // 16 MB  z = W_out @ x (pre-upsample!)

// ---------------------------------------------------------------------------
// 1x1 conv as GEMM, 4 contiguous pixels per thread (float4), MTILE output
// channels per block.  Weights transposed in smem ([C][MTILE], m contiguous)
// so ulonglong2 LDS.128 yields pre-packed (w_m, w_m+1) f32x2 operands.
// Inner loop per c: 1 LDG.128 + 4 splats(ALU) + MTILE/4 LDS.128 + 2*MTILE FFMA2.
// ---------------------------------------------------------------------------
template<int MTILE>
__global__ void __launch_bounds__(256) gemm1x1_v(
        const float* __restrict__ X, const float* __restrict__ Wm,
        const float* __restrict__ bias, float* __restrict__ out,
        int C, int M) {
    __shared__ float sWt[256 * MTILE];   // [C][MTILE]
    const int m0 = blockIdx.y * MTILE;
    for (int idx = threadIdx.x; idx < C * MTILE; idx += 256)
        sWt[idx] = Wm[(m0 + (idx % MTILE)) * C + (idx / MTILE)];
    __syncthreads();

    const int p0  = (blockIdx.x * 256 + threadIdx.x) * 4;  // 4 contiguous pixels
    const int n   = p0 >> 12;
    const int pix = p0 & 4095;
    const float4* xb = (const float4*)(X + (size_t)n * C * HW) + (pix >> 2);

    // acc2[mp][p] = (acc[2mp][pixel p], acc[2mp+1][pixel p])
    u64 acc2[MTILE / 2][4];
#pragma unroll
    for (int mp = 0; mp < MTILE / 2; mp++) {
        float b0 = bias ? bias[m0 + 2 * mp]     : 0.0f;
        float b1 = bias ? bias[m0 + 2 * mp + 1] : 0.0f;
        u64 bp = pack2(b0, b1);
#pragma unroll
        for (int p = 0; p < 4; p++) acc2[mp][p] = bp;
    }

    const ulonglong2* sW2 = (const ulonglong2*)sWt;   // [C][MTILE/4]
#pragma unroll 4
    for (int c = 0; c < C; c++) {
        float4 xv = xb[c * (HW / 4)];
        u64 sx0 = splat2(xv.x), sx1 = splat2(xv.y);
        u64 sx2 = splat2(xv.z), sx3 = splat2(xv.w);
#pragma unroll
        for (int j = 0; j < MTILE / 4; j++) {
            ulonglong2 wv = sW2[c * (MTILE / 4) + j];
            fma2(acc2[2*j][0], sx0, wv.x);
            fma2(acc2[2*j][1], sx1, wv.x);
            fma2(acc2[2*j][2], sx2, wv.x);
            fma2(acc2[2*j][3], sx3, wv.x);
            fma2(acc2[2*j+1][0], sx0, wv.y);
            fma2(acc2[2*j+1][1], sx1, wv.y);
            fma2(acc2[2*j+1][2], sx2, wv.y);
            fma2(acc2[2*j+1][3], sx3, wv.y);
        }
    }

    float4* ob = (float4*)(out + (size_t)n * M * HW) + (pix >> 2);
#pragma unroll
    for (int mp = 0; mp < MTILE / 2; mp++) {
        float2 q0 = unpack2(acc2[mp][0]), q1 = unpack2(acc2[mp][1]);
        float2 q2 = unpack2(acc2[mp][2]), q3 = unpack2(acc2[mp][3]);
        ob[(m0 + 2 * mp    ) * (HW / 4)] = make_float4(q0.x, q1.x, q2.x, q3.x);
        ob[(m0 + 2 * mp + 1) * (HW / 4)] = make_float4(q0.y, q1.y, q2.y, q3.y);
    }
}

// ---------------------------------------------------------------------------
// 3x3 encoder conv  t[4,64,64,64] -> e[4,100,64,64], SAME padding.
// 16x32 spatial tile, 2 output rows per thread.  Weights staged [m][tap][q]
// with q contiguous -> LDS.128 yields two pre-packed (w_q, w_q+1) pairs.
// Accumulators packed over q-pairs; t/u taps splatted once per (m,tap).
// ---------------------------------------------------------------------------
#define QC  20
#define ICC 8

__global__ void __launch_bounds__(256) enc_conv_kernel(
        const float* __restrict__ T, const float* __restrict__ Wenc,
        const float* __restrict__ benc, float* __restrict__ E) {
    __shared__ float sT[ICC * 18 * 34];   // 4896 floats
    __shared__ float sW[ICC * 9 * QC];    // 1440 floats: [m][tap][q]

    const int wtile = blockIdx.x;          // 0..1  (32-wide tiles)
    const int n     = blockIdx.y >> 2;     // 0..3
    const int htile = blockIdx.y & 3;      // 0..3  (16-high tiles)
    const int ch0   = blockIdx.z * QC;
    const int tid   = threadIdx.x;
    const int ty    = tid >> 5, tx = tid & 31;
    const int h0 = htile * 16 - 1, w0 = wtile * 32 - 1;

    // acc over q-pairs, separately for the two output rows
    u64 acc_t[QC / 2], acc_u[QC / 2];
#pragma unroll
    for (int qp = 0; qp < QC / 2; qp++) {
        u64 bp = pack2(benc[ch0 + 2 * qp], benc[ch0 + 2 * qp + 1]);
        acc_t[qp] = bp; acc_u[qp] = bp;
    }

    for (int icc = 0; icc < CM / ICC; icc++) {
        const int ic0 = icc * ICC;
        __syncthreads();
        for (int idx = tid; idx < ICC * 18 * 34; idx += 256) {
            int ch = idx / 612, rem = idx % 612;
            int r = rem / 34, col = rem % 34;
            int gr = h0 + r, gc = w0 + col;
            float v = 0.0f;
            if ((unsigned)gr < HH && (unsigned)gc < WW)
                v = T[((n * CM + ic0 + ch) * HH + gr) * WW + gc];
            sT[idx] = v;
        }
        for (int idx = tid; idx < ICC * 9 * QC; idx += 256) {
            int m = idx / (9 * QC), rem = idx % (9 * QC);
            int tap = rem / QC, q = rem % QC;
            sW[idx] = Wenc[((ch0 + q) * CM + ic0 + m) * 9 + tap];
        }
        __syncthreads();

        for (int m = 0; m < ICC; m++) {
            const float* tb = sT + m * 612 + ty * 34 + tx;
            const float* ub = tb + 8 * 34;
#pragma unroll
            for (int ki = 0; ki < 3; ki++) {
#pragma unroll
                for (int kj = 0; kj < 3; kj++) {
                    const int tap = ki * 3 + kj;
                    u64 at = splat2(tb[ki * 34 + kj]);
                    u64 au = splat2(ub[ki * 34 + kj]);
                    const ulonglong2* wb =
                        (const ulonglong2*)(sW + (m * 9 + tap) * QC);
#pragma unroll
                    for (int g = 0; g < QC / 4; g++) {
                        ulonglong2 wv = wb[g];
                        fma2(acc_t[2 * g],     at, wv.x);
                        fma2(acc_t[2 * g + 1], at, wv.y);
                        fma2(acc_u[2 * g],     au, wv.x);
                        fma2(acc_u[2 * g + 1], au, wv.y);
                    }
                }
            }
        }
    }

    const int h = htile * 16 + ty, w = wtile * 32 + tx;
#pragma unroll
    for (int qp = 0; qp < QC / 2; qp++) {
        float2 vt = unpack2(acc_t[qp]);
        float2 vu = unpack2(acc_u[qp]);
        E[((n * EOUT + ch0 + 2*qp    ) * HH + h    ) * WW + w] = vt.x;
        E[((n * EOUT + ch0 + 2*qp + 1) * HH + h    ) * WW + w] = vt.y;
        E[((n * EOUT + ch0 + 2*qp    ) * HH + h + 8) * WW + w] = vu.x;
        E[((n * EOUT + ch0 + 2*qp + 1) * HH + h + 8) * WW + w] = vu.y;
    }
}

// ---------------------------------------------------------------------------
// Fused softmax + reassembly + pixel-shuffle + bias, double-buffered staging.
// (unchanged from R3 -- issue-slot bound, f32x2 saves nothing here)
// ---------------------------------------------------------------------------
__global__ void __launch_bounds__(256) carafe_kernel(
        const float* __restrict__ E, const float* __restrict__ Z,
        const float* __restrict__ bout, float* __restrict__ out) {
    __shared__ float sZ[2][4 * 5 * 72];

    const int nh = blockIdx.x;
    const int n  = nh >> 6;
    const int h  = nh & 63;
    const int chalf = blockIdx.y;
    const int tid   = threadIdx.x;
    const int w     = tid & 63;
    const int psel  = (tid >> 6) & 1;
    const int cslot = tid >> 7;

    const int p0 = 2 * psel;
    float kr[50];
    const float* eb = E + (size_t)n * EOUT * HW + h * WW + w;
#pragma unroll
    for (int k = 0; k < 25; k++) {
        kr[k * 2 + 0] = eb[(k * 4 + p0 + 0) * HW];
        kr[k * 2 + 1] = eb[(k * 4 + p0 + 1) * HW];
    }
#pragma unroll
    for (int pp = 0; pp < 2; pp++) {
        float mx = kr[pp];
#pragma unroll
        for (int k = 1; k < 25; k++) mx = fmaxf(mx, kr[k * 2 + pp]);
        float s = 0.0f;
#pragma unroll
        for (int k = 0; k < 25; k++) {
            float ex = __expf(kr[k * 2 + pp] - mx);
            kr[k * 2 + pp] = ex;
            s += ex;
        }
        float inv = 1.0f / s;
#pragma unroll
        for (int k = 0; k < 25; k++) kr[k * 2 + pp] *= inv;
    }

    const int lane64 = tid & 63;
    const int sch    = tid >> 6;
    const int hch    = tid >> 5;
    const int t2     = tid & 31;
    float2* op = (float2*)out;

    auto stage = [&](int it, int buf) {
        const int cbase = chalf * 128 + it * 4;
        float4* sZ4 = (float4*)sZ[buf];
        const float4* zc = (const float4*)(Z +
            ((size_t)(n * OUTC + cbase + sch) * HH) * WW);
        int r = lane64 >> 4, g = lane64 & 15;
        int row = h - 2 + r;
        float4 v = make_float4(0.f, 0.f, 0.f, 0.f);
        if ((unsigned)row < HH) v = zc[row * 16 + g];
        sZ4[sch * 90 + r * 18 + 1 + g] = v;
        if (lane64 < 16) {
            int row2 = h + 2;
            float4 v2 = make_float4(0.f, 0.f, 0.f, 0.f);
            if ((unsigned)row2 < HH) v2 = zc[row2 * 16 + lane64];
            sZ4[sch * 90 + 4 * 18 + 1 + lane64] = v2;
        }
        if (tid < 128 && t2 < 20) {
            int rr = t2 >> 2, cc = t2 & 3;
            int hrow = h - 2 + rr;
            int wc = (cc < 2) ? cc - 2 : 62 + cc;
            float hv = 0.0f;
            if ((unsigned)hrow < HH && (unsigned)wc < WW)
                hv = Z[((size_t)(n * OUTC + cbase + hch) * HH + hrow) * WW + wc];
            sZ[buf][hch * 360 + rr * 72 + ((cc < 2) ? cc + 2 : 66 + cc)] = hv;
        }
    };

    stage(0, 0);
    __syncthreads();

    for (int it = 0; it < 32; it++) {
        if (it < 31) stage(it + 1, (it + 1) & 1);

        const int cbase = chalf * 128 + it * 4;
        const int c0 = cbase + 2 * cslot;
        const float* zb = sZ[it & 1] + (2 * cslot) * 360 + (w + 2);
        float a00 = 0.f, a01 = 0.f, a10 = 0.f, a11 = 0.f;
#pragma unroll
        for (int ki = 0; ki < 5; ki++) {
#pragma unroll
            for (int kj = 0; kj < 5; kj++) {
                int kk = ki * 5 + kj;
                float z0 = zb[ki * 72 + kj];
                float z1 = zb[360 + ki * 72 + kj];
                a00 += z0 * kr[kk * 2 + 0];
                a01 += z0 * kr[kk * 2 + 1];
                a10 += z1 * kr[kk * 2 + 0];
                a11 += z1 * kr[kk * 2 + 1];
            }
        }
        float b0 = __ldg(bout + c0), b1 = __ldg(bout + c0 + 1);
        int row = 2 * h + psel;
        op[((n * OUTC + c0    ) * 128 + row) * 64 + w] = make_float2(a00 + b0, a01 + b0);
        op[((n * OUTC + c0 + 1) * 128 + row) * 64 + w] = make_float2(a10 + b1, a11 + b1);
        __syncthreads();
    }
}

// ---------------------------------------------------------------------------
extern "C" void kernel_launch(void* const* d_in, const int* in_sizes, int n_in,
                              void* d_out, int out_size) {
    const float* x  = (const float*)d_in[0];
    const float* Wd = (const float*)d_in[1];
    const float* bd = (const float*)d_in[2];
    const float* We = (const float*)d_in[3];
    const float* be = (const float*)d_in[4];
    const float* Wo = (const float*)d_in[5];
    const float* bo = (const float*)d_in[6];
    float* out = (float*)d_out;

    static float* gt = nullptr;
    static float* ge = nullptr;
    static float* gz = nullptr;
    static cudaStream_t s2;
    static cudaEvent_t ev_fork, ev_join;
    if (!gt) {
        cudaGetSymbolAddress((void**)&gt, g_t);
        cudaGetSymbolAddress((void**)&ge, g_e);
        cudaGetSymbolAddress((void**)&gz, g_z);
        cudaStreamCreateWithFlags(&s2, cudaStreamNonBlocking);
        cudaEventCreateWithFlags(&ev_fork, cudaEventDisableTiming);
        cudaEventCreateWithFlags(&ev_join, cudaEventDisableTiming);
    }

    // Fork: z = W_out @ x is independent of the t/e path -> run concurrently.
    cudaEventRecord(ev_fork, 0);
    cudaStreamWaitEvent(s2, ev_fork, 0);
    gemm1x1_v<16><<<dim3(16, 16), 256, 0, s2>>>(x, Wo, nullptr, gz, CIN, OUTC);
    cudaEventRecord(ev_join, s2);

    // Main path: t = W_down @ x + b ; e = conv3x3(t) + b
    gemm1x1_v<8><<<dim3(16, 8), 256>>>(x, Wd, bd, gt, CIN, CM);
    enc_conv_kernel<<<dim3(2, 16, 5), 256>>>(gt, We, be, ge);

    // Join, then fused reassembly.
    cudaStreamWaitEvent(0, ev_join, 0);
    carafe_kernel<<<dim3(256, 2), 256>>>(ge, gz, bo, out);
}